// round 10
// baseline (speedup 1.0000x reference)
#include <cuda_runtime.h>

#define NMAX  100000
#define EMAX  3200000
#define NF    512
#define NH    8
#define NC    16

// ---------------- scratch (no allocations allowed) ----------------
__device__ float g_s1[NMAX * NH];          // x @ W1 (pre-spmm)
__device__ float g_xr[NMAX * NH];          // affine(relu(bi-interaction))
__device__ float g_s2[NMAX * NC];          // h @ W2
__device__ int   g_cnt[NMAX];              // per-row degree
__device__ int   g_offs[NMAX];             // CSR row range start (arbitrary order)
__device__ int   g_cur[NMAX];              // scatter cursors
__device__ int   g_total;                  // global range allocator
__device__ unsigned long long g_ep[EMAX];  // packed edges: lo=col, hi=val bits
__device__ float g_wpack[3 * NH * NF];     // staging for constant upload

// weights in constant bank: [mat][h][k], mat0=W1, mat1=V, mat2=V*V (48 KB)
__constant__ float c_w[3 * NH * NF];

typedef unsigned long long u64;

// ---------------- f32x2 helpers (FFMA2 = full-rate fp32 on sm_103a) ---
#define UNPACK2(lo, hi, in) \
    asm("mov.b64 {%0, %1}, %2;" : "=f"(lo), "=f"(hi) : "l"(in))
#define MUL2(out, a, b) \
    asm("mul.rn.f32x2 %0, %1, %2;" : "=l"(out) : "l"(a), "l"(b))
#define FMA2(acc, a, b) \
    asm("fma.rn.f32x2 %0, %1, %2, %0;" : "+l"(acc) : "l"(a), "l"(b))

// =====================================================================
// launch 0: pack weights (transpose + square V) into staging buffer
// =====================================================================
__global__ void k_prep(const float* __restrict__ W1, const float* __restrict__ V) {
    int i = blockIdx.x * blockDim.x + threadIdx.x;
    if (i < NF * NH) {
        int k = i >> 3, h = i & 7;
        float a = W1[i];
        float b = V[i];
        g_wpack[h * NF + k]                = a;
        g_wpack[NH * NF + h * NF + k]      = b;
        g_wpack[2 * NH * NF + h * NF + k]  = b * b;
    }
}

// =====================================================================
// launch 1: zero counters
// =====================================================================
__global__ void k_zero(int n) {
    int i = blockIdx.x * blockDim.x + threadIdx.x;
    int i4 = i * 4;
    if (i4 + 3 < n) {
        *(int4*)(g_cnt + i4) = make_int4(0, 0, 0, 0);
    } else {
        for (int q = 0; q < 4; q++) if (i4 + q < n) g_cnt[i4 + q] = 0;
    }
    if (i == 0) g_total = 0;
}

// =====================================================================
// launch 2: degree histogram (simple form — R5 was fastest)
// =====================================================================
__global__ void k_hist(const int* __restrict__ rows, int e) {
    int i = blockIdx.x * blockDim.x + threadIdx.x;
    if (i < e) atomicAdd(&g_cnt[rows[i]], 1);
}

// =====================================================================
// launch 3 (PROFILED SLOT): gemmA v6 — weights in constant (uniform pipe),
// smem holds only double-buffered x. 128 thr, 5 blocks/SM, 20 warps/SM.
// Crossbar per warp-4k: ~8 wf (x only). FMA 13 cyc. -> FMA/issue bound.
// =====================================================================
#define KCHUNK 16
#define XPITCH 20   // 16 + 4 pad: 16B aligned; 20i mod 32 -> conflict-free LDS.128

__global__ void __launch_bounds__(128, 5) k_gemmA(
    const float* __restrict__ x, const float* __restrict__ gamma,
    const float* __restrict__ beta, int n)
{
    __shared__ float xs[2][128 * XPITCH];   // 2 x 10240 B
    const int t = threadIdx.x;
    const int ntiles = (n + 127) >> 7;

    for (int tile = blockIdx.x; tile < ntiles; tile += gridDim.x) {
        const int nb = tile << 7;

        // prologue: prefetch chunk 0 (coalesced: 4 lanes x 16B per node row)
        float4 pf[4];
#pragma unroll
        for (int q = 0; q < 4; q++) {
            int idx = t + 128 * q;
            int row = idx >> 2, f = idx & 3;
            int gn = nb + row;
            pf[q] = make_float4(0.f, 0.f, 0.f, 0.f);
            if (gn < n) pf[q] = *(const float4*)(x + (size_t)gn * NF + f * 4);
        }

        u64 a1[8], av[8], a2[8];
#pragma unroll
        for (int h = 0; h < 8; h++) { a1[h] = 0ull; av[h] = 0ull; a2[h] = 0ull; }

        for (int c = 0; c < NF / KCHUNK; c++) {
            float* xb = xs[c & 1];
            // store prefetched chunk c
#pragma unroll
            for (int q = 0; q < 4; q++) {
                int idx = t + 128 * q;
                int row = idx >> 2, f = idx & 3;
                *(float4*)(xb + row * XPITCH + f * 4) = pf[q];
            }
            __syncthreads();
            // prefetch chunk c+1 (overlapped with compute below)
            if (c + 1 < NF / KCHUNK) {
                int kc = (c + 1) * KCHUNK;
#pragma unroll
                for (int q = 0; q < 4; q++) {
                    int idx = t + 128 * q;
                    int row = idx >> 2, f = idx & 3;
                    int gn = nb + row;
                    pf[q] = make_float4(0.f, 0.f, 0.f, 0.f);
                    if (gn < n) pf[q] = *(const float4*)(x + (size_t)gn * NF + kc + f * 4);
                }
            }
            // compute chunk c: weights from constant (uniform index -> LDCU)
            const float* wc = c_w + c * KCHUNK;
#pragma unroll
            for (int kk = 0; kk < KCHUNK; kk += 4) {
                ulonglong2 xp = *(const ulonglong2*)(xb + t * XPITCH + kk);
                u64 sqA, sqB;
                MUL2(sqA, xp.x, xp.x);
                MUL2(sqB, xp.y, xp.y);
                const float* wb = wc + kk;
#pragma unroll
                for (int h = 0; h < 8; h++) {
                    ulonglong2 w1p = *(const ulonglong2*)(wb + h * NF);
                    ulonglong2 wvp = *(const ulonglong2*)(wb + (NH + h) * NF);
                    ulonglong2 w2p = *(const ulonglong2*)(wb + (2 * NH + h) * NF);
                    FMA2(a1[h], xp.x, w1p.x); FMA2(a1[h], xp.y, w1p.y);
                    FMA2(av[h], xp.x, wvp.x); FMA2(av[h], xp.y, wvp.y);
                    FMA2(a2[h], sqA,  w2p.x); FMA2(a2[h], sqB,  w2p.y);
                }
            }
        }

        int node = nb + t;
        if (node < n) {
#pragma unroll
            for (int h = 0; h < 8; h++) {
                float l0, l1;
                UNPACK2(l0, l1, a1[h]); float s1v  = l0 + l1;
                UNPACK2(l0, l1, av[h]); float xv   = l0 + l1;
                UNPACK2(l0, l1, a2[h]); float x2v2 = l0 + l1;
                float r = 0.5f * (xv * xv - x2v2);
                r = r > 0.f ? r : 0.f;
                g_s1[(size_t)node * NH + h] = s1v;
                g_xr[(size_t)node * NH + h] = gamma[h] * r + beta[h];
            }
        }
        __syncthreads();
    }
}

// =====================================================================
// launch 4: allocate contiguous per-row ranges (block scan + 1 atomic/block)
// =====================================================================
__global__ void __launch_bounds__(256) k_alloc(int n) {
    __shared__ int wsum[8];
    __shared__ int wpref[8];
    __shared__ int blockBase;
    int t = threadIdx.x;
    int lane = t & 31, wid = t >> 5;
    int base = blockIdx.x * 1024 + t * 4;

    int v[4]; int s = 0;
#pragma unroll
    for (int q = 0; q < 4; q++) { int i = base + q; v[q] = (i < n) ? g_cnt[i] : 0; s += v[q]; }

    int sc = s;
#pragma unroll
    for (int d = 1; d < 32; d <<= 1) {
        int u = __shfl_up_sync(~0u, sc, d);
        if (lane >= d) sc += u;
    }
    if (lane == 31) wsum[wid] = sc;
    __syncthreads();
    if (t == 0) {
        int run = 0;
#pragma unroll
        for (int w = 0; w < 8; w++) { wpref[w] = run; run += wsum[w]; }
        blockBase = atomicAdd(&g_total, run);
    }
    __syncthreads();

    int run = blockBase + wpref[wid] + (sc - s);
#pragma unroll
    for (int q = 0; q < 4; q++) {
        int i = base + q;
        if (i < n) {
            g_offs[i] = run;
            g_cur[i]  = run;
            run += v[q];
        }
    }
}

// =====================================================================
// launch 5: scatter edges into CSR order (simple form — R5 was fastest)
// =====================================================================
__global__ void k_scatter(const int* __restrict__ rows, const int* __restrict__ cols,
                          const float* __restrict__ vals, int e) {
    int i = blockIdx.x * blockDim.x + threadIdx.x;
    if (i >= e) return;
    int r = rows[i];
    int pos = atomicAdd(&g_cur[r], 1);
    u64 p = ((u64)__float_as_uint(vals[i]) << 32) | (unsigned int)cols[i];
    g_ep[pos] = p;
}

// =====================================================================
// launch 6: pull-SpMM #1 fused with bias/relu/merge/h@W2 (R5 form)
// =====================================================================
__global__ void __launch_bounds__(256) k_spmm1mid(
    const float* __restrict__ b1, const float* __restrict__ W2, int n)
{
    __shared__ float w2s[NH * NC];
    __shared__ float b1s[NH];
    int t = threadIdx.x;
    if (t < NH * NC) w2s[t] = W2[t];
    if (t < NH)      b1s[t] = b1[t];
    __syncthreads();

    int j   = t & 7;
    int grp = t >> 3;
    int r   = blockIdx.x * 32 + grp;
    bool valid = r < n;
    int rc = valid ? r : (n - 1);
    int start = g_offs[rc];
    int end   = start + g_cnt[rc];

    float acc = 0.f, accB = 0.f;
    int i = start;
    for (; i + 2 <= end; i += 2) {
        u64 p0 = g_ep[i], p1 = g_ep[i + 1];
        int   c0 = (int)(unsigned)p0,  c1 = (int)(unsigned)p1;
        float v0 = __uint_as_float((unsigned)(p0 >> 32));
        float v1 = __uint_as_float((unsigned)(p1 >> 32));
        acc  = fmaf(v0, g_s1[(size_t)c0 * NH + j], acc);
        accB = fmaf(v1, g_s1[(size_t)c1 * NH + j], accB);
    }
    if (i < end) {
        u64 p0 = g_ep[i];
        float v0 = __uint_as_float((unsigned)(p0 >> 32));
        acc = fmaf(v0, g_s1[(size_t)((int)(unsigned)p0) * NH + j], acc);
    }
    acc += accB;

    float l = acc + b1s[j];
    l = l > 0.f ? l : 0.f;
    float h = 0.5f * (l + (valid ? g_xr[(size_t)r * NH + j] : 0.f));

    float o0 = 0.f, o1 = 0.f;
#pragma unroll
    for (int jj = 0; jj < 8; jj++) {
        float hv = __shfl_sync(0xffffffffu, h, jj, 8);
        o0 = fmaf(hv, w2s[jj * NC + j],     o0);
        o1 = fmaf(hv, w2s[jj * NC + j + 8], o1);
    }
    if (valid) {
        g_s2[(size_t)r * NC + j]     = o0;
        g_s2[(size_t)r * NC + j + 8] = o1;
    }
}

// =====================================================================
// launch 7: pull-SpMM #2 fused with +b2 and log_softmax (R5 form)
// =====================================================================
__global__ void __launch_bounds__(256) k_spmm2lsm(
    const float* __restrict__ b2, float* __restrict__ out, int n)
{
    __shared__ float b2s[NC];
    int t = threadIdx.x;
    if (t < NC) b2s[t] = b2[t];
    __syncthreads();

    int c   = t & 15;
    int grp = t >> 4;
    int r   = blockIdx.x * 16 + grp;
    bool valid = r < n;
    int rc = valid ? r : (n - 1);
    int start = g_offs[rc];
    int end   = start + g_cnt[rc];

    float acc = 0.f, accB = 0.f;
    int i = start;
    for (; i + 2 <= end; i += 2) {
        u64 p0 = g_ep[i], p1 = g_ep[i + 1];
        int   c0 = (int)(unsigned)p0,  c1 = (int)(unsigned)p1;
        float v0 = __uint_as_float((unsigned)(p0 >> 32));
        float v1 = __uint_as_float((unsigned)(p1 >> 32));
        acc  = fmaf(v0, g_s2[(size_t)c0 * NC + c], acc);
        accB = fmaf(v1, g_s2[(size_t)c1 * NC + c], accB);
    }
    if (i < end) {
        u64 p0 = g_ep[i];
        float v0 = __uint_as_float((unsigned)(p0 >> 32));
        acc = fmaf(v0, g_s2[(size_t)((int)(unsigned)p0) * NC + c], acc);
    }
    float v = acc + accB + b2s[c];

    float m = v;
#pragma unroll
    for (int d = 8; d; d >>= 1) m = fmaxf(m, __shfl_xor_sync(~0u, m, d, 16));
    float s = __expf(v - m);
#pragma unroll
    for (int d = 8; d; d >>= 1) s += __shfl_xor_sync(~0u, s, d, 16);
    if (valid) out[(size_t)r * NC + c] = v - m - __logf(s);
}

// ---------------- launcher -------------------------------------------
extern "C" void kernel_launch(void* const* d_in, const int* in_sizes, int n_in,
                              void* d_out, int out_size)
{
    const float* x     = (const float*)d_in[0];
    const int*   rows  = (const int*)d_in[1];
    const int*   cols  = (const int*)d_in[2];
    const float* vals  = (const float*)d_in[3];
    const float* W1    = (const float*)d_in[4];
    const float* b1    = (const float*)d_in[5];
    const float* W2    = (const float*)d_in[6];
    const float* b2    = (const float*)d_in[7];
    const float* V     = (const float*)d_in[8];
    const float* gamma = (const float*)d_in[9];
    const float* beta  = (const float*)d_in[10];
    float* out = (float*)d_out;

    int n = in_sizes[0] / NF;   // 100000
    int e = in_sizes[1];        // 3200000

    // launch 0: pack weights into staging
    k_prep<<<(NF * NH + 255) / 256, 256>>>(W1, V);

    // upload staging -> constant bank (D2D async copy, graph-capturable)
    void* csym = nullptr;
    void* gsym = nullptr;
    cudaGetSymbolAddress(&csym, c_w);
    cudaGetSymbolAddress(&gsym, g_wpack);
    cudaMemcpyAsync(csym, gsym, 3 * NH * NF * sizeof(float),
                    cudaMemcpyDeviceToDevice, 0);

    // launch 1-2: CSR counters
    k_zero<<<(n + 1023) / 1024, 256>>>(n);
    k_hist<<<(e + 255) / 256, 256>>>(rows, e);

    // launch 3 (profiled slot): fused input GEMM v6 (constant weights)
    k_gemmA<<<740, 128>>>(x, gamma, beta, n);

    // launch 4: allocate CSR ranges
    k_alloc<<<(n + 1023) / 1024, 256>>>(n);

    // launch 5: scatter edges into CSR order
    k_scatter<<<(e + 255) / 256, 256>>>(rows, cols, vals, e);

    // launch 6: pull SpMM 1 + mid fusion
    k_spmm1mid<<<(n + 31) / 32, 256>>>(b1, W2, n);

    // launch 7: pull SpMM 2 + bias + log_softmax
    k_spmm2lsm<<<(n + 15) / 16, 256>>>(b2, out, n);
}

// round 11
// speedup vs baseline: 1.1643x; 1.1643x over previous
#include <cuda_runtime.h>

#define NMAX  100000
#define EMAX  3200000
#define NF    512
#define NH    8
#define NC    16

// ---------------- scratch (no allocations allowed) ----------------
__device__ float g_s1[NMAX * NH];          // x @ W1 (pre-spmm)
__device__ float g_xr[NMAX * NH];          // affine(relu(bi-interaction))
__device__ float g_s2[NMAX * NC];          // h @ W2
__device__ int   g_cnt[NMAX];              // per-row degree
__device__ int   g_offs[NMAX];             // CSR row range start (arbitrary order)
__device__ int   g_cur[NMAX];              // scatter cursors
__device__ int   g_total;                  // global range allocator
__device__ unsigned long long g_ep[EMAX];  // packed edges: lo=col, hi=val bits

typedef unsigned long long u64;

// ---------------- f32x2 helpers (FFMA2 = full-rate fp32 on sm_103a) ---
#define UNPACK2(lo, hi, in) \
    asm("mov.b64 {%0, %1}, %2;" : "=f"(lo), "=f"(hi) : "l"(in))
#define MUL2(out, a, b) \
    asm("mul.rn.f32x2 %0, %1, %2;" : "=l"(out) : "l"(a), "l"(b))
#define FMA2(acc, a, b) \
    asm("fma.rn.f32x2 %0, %1, %2, %0;" : "+l"(acc) : "l"(a), "l"(b))

// =====================================================================
// launch 0: zero counters
// =====================================================================
__global__ void k_zero(int n) {
    int i = blockIdx.x * blockDim.x + threadIdx.x;
    int i4 = i * 4;
    if (i4 + 3 < n) {
        *(int4*)(g_cnt + i4) = make_int4(0, 0, 0, 0);
    } else {
        for (int q = 0; q < 4; q++) if (i4 + q < n) g_cnt[i4 + q] = 0;
    }
    if (i == 0) g_total = 0;
}

// =====================================================================
// launch 1: degree histogram
// =====================================================================
__global__ void k_hist(const int* __restrict__ rows, int e) {
    int i = blockIdx.x * blockDim.x + threadIdx.x;
    if (i < e) atomicAdd(&g_cnt[rows[i]], 1);
}

// =====================================================================
// launch 2: allocate contiguous per-row ranges (block scan + 1 atomic/block)
// =====================================================================
__global__ void __launch_bounds__(256) k_alloc(int n) {
    __shared__ int wsum[8];
    __shared__ int wpref[8];
    __shared__ int blockBase;
    int t = threadIdx.x;
    int lane = t & 31, wid = t >> 5;
    int base = blockIdx.x * 1024 + t * 4;

    int v[4]; int s = 0;
#pragma unroll
    for (int q = 0; q < 4; q++) { int i = base + q; v[q] = (i < n) ? g_cnt[i] : 0; s += v[q]; }

    int sc = s;
#pragma unroll
    for (int d = 1; d < 32; d <<= 1) {
        int u = __shfl_up_sync(~0u, sc, d);
        if (lane >= d) sc += u;
    }
    if (lane == 31) wsum[wid] = sc;
    __syncthreads();
    if (t == 0) {
        int run = 0;
#pragma unroll
        for (int w = 0; w < 8; w++) { wpref[w] = run; run += wsum[w]; }
        blockBase = atomicAdd(&g_total, run);
    }
    __syncthreads();

    int run = blockBase + wpref[wid] + (sc - s);
#pragma unroll
    for (int q = 0; q < 4; q++) {
        int i = base + q;
        if (i < n) {
            g_offs[i] = run;
            g_cur[i]  = run;
            run += v[q];
        }
    }
}

// =====================================================================
// launch 3 (PROFILED SLOT): gemmA v7 — 2 nodes/thread, weights in SMEM
// 256-node tile per 128-thread block. Per warp-4k-step: 24 broadcast
// weight wf amortized over 64 nodes, ~40 wf crossbar vs 96 FFMA2
// (48 SM-cyc) -> FMA-bound. 3 blocks/SM (68 KB smem each).
// =====================================================================
#define TILEN  256
#define KCHUNK 16
#define XPITCH 20   // 16 + 4 pad: 16B-aligned, near-conflict-free

__global__ void __launch_bounds__(128, 3) k_gemmA(
    const float* __restrict__ x, const float* __restrict__ W1,
    const float* __restrict__ V, const float* __restrict__ gamma,
    const float* __restrict__ beta, int n)
{
    extern __shared__ float sm[];
    float* wT = sm;                    // [24][512]   48 KB
    float* xs = sm + 24 * NF;          // [256][20]   20 KB
    const int t = threadIdx.x;
    const int nb = blockIdx.x * TILEN;

    // stage combined weights once per block, transposed to [out][k]
    for (int i = t; i < NF * NH; i += 128) {
        int k = i >> 3, h = i & 7;
        float a = W1[i];
        float b = V[i];
        wT[h * NF + k]             = a;
        wT[(NH + h) * NF + k]      = b;
        wT[(2 * NH + h) * NF + k]  = b * b;
    }

    u64 a1[2][8], av[2][8], a2[2][8];
#pragma unroll
    for (int nd = 0; nd < 2; nd++)
#pragma unroll
        for (int h = 0; h < 8; h++) { a1[nd][h] = 0ull; av[nd][h] = 0ull; a2[nd][h] = 0ull; }

    for (int kc = 0; kc < NF; kc += KCHUNK) {
        __syncthreads();
        // stage x chunk [256 nodes][16 k]: 1024 float4 over 128 threads
#pragma unroll
        for (int q = 0; q < 8; q++) {
            int idx = t + 128 * q;
            int row = idx >> 2, f = idx & 3;
            int gn = nb + row;
            float4 val = make_float4(0.f, 0.f, 0.f, 0.f);
            if (gn < n) val = *(const float4*)(x + (size_t)gn * NF + kc + f * 4);
            *(float4*)(xs + row * XPITCH + f * 4) = val;
        }
        __syncthreads();

#pragma unroll
        for (int kk = 0; kk < KCHUNK; kk += 4) {
            ulonglong2 xp0 = *(const ulonglong2*)(xs + t * XPITCH + kk);
            ulonglong2 xp1 = *(const ulonglong2*)(xs + (t + 128) * XPITCH + kk);
            u64 s0A, s0B, s1A, s1B;
            MUL2(s0A, xp0.x, xp0.x); MUL2(s0B, xp0.y, xp0.y);
            MUL2(s1A, xp1.x, xp1.x); MUL2(s1B, xp1.y, xp1.y);
            const float* wb = wT + kc + kk;
#pragma unroll
            for (int h = 0; h < 8; h++) {
                ulonglong2 w1p = *(const ulonglong2*)(wb + h * NF);             // broadcast
                ulonglong2 wvp = *(const ulonglong2*)(wb + (NH + h) * NF);      // broadcast
                ulonglong2 w2p = *(const ulonglong2*)(wb + (2 * NH + h) * NF);  // broadcast
                FMA2(a1[0][h], xp0.x, w1p.x); FMA2(a1[0][h], xp0.y, w1p.y);
                FMA2(a1[1][h], xp1.x, w1p.x); FMA2(a1[1][h], xp1.y, w1p.y);
                FMA2(av[0][h], xp0.x, wvp.x); FMA2(av[0][h], xp0.y, wvp.y);
                FMA2(av[1][h], xp1.x, wvp.x); FMA2(av[1][h], xp1.y, wvp.y);
                FMA2(a2[0][h], s0A,   w2p.x); FMA2(a2[0][h], s0B,   w2p.y);
                FMA2(a2[1][h], s1A,   w2p.x); FMA2(a2[1][h], s1B,   w2p.y);
            }
        }
    }

#pragma unroll
    for (int nd = 0; nd < 2; nd++) {
        int node = nb + t + nd * 128;
        if (node < n) {
            float s1o[8], xro[8];
#pragma unroll
            for (int h = 0; h < 8; h++) {
                float l0, l1;
                UNPACK2(l0, l1, a1[nd][h]); s1o[h] = l0 + l1;
                UNPACK2(l0, l1, av[nd][h]); float xv   = l0 + l1;
                UNPACK2(l0, l1, a2[nd][h]); float x2v2 = l0 + l1;
                float r = 0.5f * (xv * xv - x2v2);
                r = r > 0.f ? r : 0.f;
                xro[h] = gamma[h] * r + beta[h];
            }
            *(float4*)(g_s1 + (size_t)node * NH)     = make_float4(s1o[0], s1o[1], s1o[2], s1o[3]);
            *(float4*)(g_s1 + (size_t)node * NH + 4) = make_float4(s1o[4], s1o[5], s1o[6], s1o[7]);
            *(float4*)(g_xr + (size_t)node * NH)     = make_float4(xro[0], xro[1], xro[2], xro[3]);
            *(float4*)(g_xr + (size_t)node * NH + 4) = make_float4(xro[4], xro[5], xro[6], xro[7]);
        }
    }
}

// =====================================================================
// launch 4: scatter edges into CSR order
// =====================================================================
__global__ void k_scatter(const int* __restrict__ rows, const int* __restrict__ cols,
                          const float* __restrict__ vals, int e) {
    int i = blockIdx.x * blockDim.x + threadIdx.x;
    if (i >= e) return;
    int r = rows[i];
    int pos = atomicAdd(&g_cur[r], 1);
    u64 p = ((u64)__float_as_uint(vals[i]) << 32) | (unsigned int)cols[i];
    g_ep[pos] = p;
}

// =====================================================================
// launch 5: pull-SpMM #1 fused with bias/relu/merge/h@W2
// =====================================================================
__global__ void __launch_bounds__(256) k_spmm1mid(
    const float* __restrict__ b1, const float* __restrict__ W2, int n)
{
    __shared__ float w2s[NH * NC];
    __shared__ float b1s[NH];
    int t = threadIdx.x;
    if (t < NH * NC) w2s[t] = W2[t];
    if (t < NH)      b1s[t] = b1[t];
    __syncthreads();

    int j   = t & 7;
    int grp = t >> 3;
    int r   = blockIdx.x * 32 + grp;
    bool valid = r < n;
    int rc = valid ? r : (n - 1);
    int start = g_offs[rc];
    int end   = start + g_cnt[rc];

    float acc = 0.f, accB = 0.f;
    int i = start;
    for (; i + 2 <= end; i += 2) {
        u64 p0 = g_ep[i], p1 = g_ep[i + 1];
        int   c0 = (int)(unsigned)p0,  c1 = (int)(unsigned)p1;
        float v0 = __uint_as_float((unsigned)(p0 >> 32));
        float v1 = __uint_as_float((unsigned)(p1 >> 32));
        acc  = fmaf(v0, g_s1[(size_t)c0 * NH + j], acc);
        accB = fmaf(v1, g_s1[(size_t)c1 * NH + j], accB);
    }
    if (i < end) {
        u64 p0 = g_ep[i];
        float v0 = __uint_as_float((unsigned)(p0 >> 32));
        acc = fmaf(v0, g_s1[(size_t)((int)(unsigned)p0) * NH + j], acc);
    }
    acc += accB;

    float l = acc + b1s[j];
    l = l > 0.f ? l : 0.f;
    float h = 0.5f * (l + (valid ? g_xr[(size_t)r * NH + j] : 0.f));

    float o0 = 0.f, o1 = 0.f;
#pragma unroll
    for (int jj = 0; jj < 8; jj++) {
        float hv = __shfl_sync(0xffffffffu, h, jj, 8);
        o0 = fmaf(hv, w2s[jj * NC + j],     o0);
        o1 = fmaf(hv, w2s[jj * NC + j + 8], o1);
    }
    if (valid) {
        g_s2[(size_t)r * NC + j]     = o0;
        g_s2[(size_t)r * NC + j + 8] = o1;
    }
}

// =====================================================================
// launch 6: pull-SpMM #2 fused with +b2 and log_softmax
// =====================================================================
__global__ void __launch_bounds__(256) k_spmm2lsm(
    const float* __restrict__ b2, float* __restrict__ out, int n)
{
    __shared__ float b2s[NC];
    int t = threadIdx.x;
    if (t < NC) b2s[t] = b2[t];
    __syncthreads();

    int c   = t & 15;
    int grp = t >> 4;
    int r   = blockIdx.x * 16 + grp;
    bool valid = r < n;
    int rc = valid ? r : (n - 1);
    int start = g_offs[rc];
    int end   = start + g_cnt[rc];

    float acc = 0.f, accB = 0.f;
    int i = start;
    for (; i + 2 <= end; i += 2) {
        u64 p0 = g_ep[i], p1 = g_ep[i + 1];
        int   c0 = (int)(unsigned)p0,  c1 = (int)(unsigned)p1;
        float v0 = __uint_as_float((unsigned)(p0 >> 32));
        float v1 = __uint_as_float((unsigned)(p1 >> 32));
        acc  = fmaf(v0, g_s2[(size_t)c0 * NC + c], acc);
        accB = fmaf(v1, g_s2[(size_t)c1 * NC + c], accB);
    }
    if (i < end) {
        u64 p0 = g_ep[i];
        float v0 = __uint_as_float((unsigned)(p0 >> 32));
        acc = fmaf(v0, g_s2[(size_t)((int)(unsigned)p0) * NC + c], acc);
    }
    float v = acc + accB + b2s[c];

    float m = v;
#pragma unroll
    for (int d = 8; d; d >>= 1) m = fmaxf(m, __shfl_xor_sync(~0u, m, d, 16));
    float s = __expf(v - m);
#pragma unroll
    for (int d = 8; d; d >>= 1) s += __shfl_xor_sync(~0u, s, d, 16);
    if (valid) out[(size_t)r * NC + c] = v - m - __logf(s);
}

// ---------------- launcher -------------------------------------------
extern "C" void kernel_launch(void* const* d_in, const int* in_sizes, int n_in,
                              void* d_out, int out_size)
{
    const float* x     = (const float*)d_in[0];
    const int*   rows  = (const int*)d_in[1];
    const int*   cols  = (const int*)d_in[2];
    const float* vals  = (const float*)d_in[3];
    const float* W1    = (const float*)d_in[4];
    const float* b1    = (const float*)d_in[5];
    const float* W2    = (const float*)d_in[6];
    const float* b2    = (const float*)d_in[7];
    const float* V     = (const float*)d_in[8];
    const float* gamma = (const float*)d_in[9];
    const float* beta  = (const float*)d_in[10];
    float* out = (float*)d_out;

    int n = in_sizes[0] / NF;   // 100000
    int e = in_sizes[1];        // 3200000

    int smem = (3 * NH * NF + TILEN * XPITCH) * (int)sizeof(float);   // 69632 B
    cudaFuncSetAttribute(k_gemmA, cudaFuncAttributeMaxDynamicSharedMemorySize, smem);

    // launch 0-2: CSR skeleton
    k_zero<<<(n + 1023) / 1024, 256>>>(n);
    k_hist<<<(e + 255) / 256, 256>>>(rows, e);
    k_alloc<<<(n + 1023) / 1024, 256>>>(n);

    // launch 3 (profiled slot): fused input GEMM v7 (2 nodes/thread)
    int ntiles = (n + TILEN - 1) / TILEN;   // 391
    k_gemmA<<<ntiles, 128, smem>>>(x, W1, V, gamma, beta, n);

    // launch 4: scatter edges into CSR order
    k_scatter<<<(e + 255) / 256, 256>>>(rows, cols, vals, e);

    // launch 5: pull SpMM 1 + mid fusion
    k_spmm1mid<<<(n + 31) / 32, 256>>>(b1, W2, n);

    // launch 6: pull SpMM 2 + bias + log_softmax
    k_spmm2lsm<<<(n + 15) / 16, 256>>>(b2, out, n);
}